// round 5
// baseline (speedup 1.0000x reference)
#include <cuda_runtime.h>
#include <cstdint>

#define BB    2048
#define SS    201
#define HALF  100
#define DD    128
#define ROWS  (BB*SS)          /* 411648 */
#define A_EL  (ROWS*DD)        /* 52697088 : elems of x_embedding (== pos_enc) */

#define EMB_BLOCKS ((ROWS*32)/256)   /* 51456 */

// scratch: visited_time as int32 for the gather (static device array: allowed)
__device__ int g_visited[ROWS];

// ---------------------------------------------------------------------------
// Kernel 1: thread-per-batch pointer chase with an O(1) top-2 via a
// recency-ordered doubly-linked list over stack slots.
//
// Stack semantics (reference): slot0 = 0.0 always; push writes time i+1
// (distinct, increasing); pop writes -0.01. top_k(...,2) indices are:
//   >=2 active pickups : (newest, 2nd newest)      [largest times]
//   1 active           : (that slot, 0)            [0.0 beats -0.01]
//   0 active           : (0, 1)                    [lowest-index -0.01]
// List: head = newest active, tail sentinel = node 0. LNK(p) packs
// next (low 8) | prev (high 8); prev==255 means "is head". A 101-bit
// register mask guards pops of never/no-longer-active slots (random
// permutation => delivery may precede its pickup; reference makes that
// a -0.01 -> -0.01 no-op).
// ---------------------------------------------------------------------------
#define CTPB 32
#define SOLSTRIDE 203   /* odd u16 stride -> bank spread */

__global__ void __launch_bounds__(CTPB)
chase_kernel(const int* __restrict__ sol32,
             float*  __restrict__ out_vt,
             float2* __restrict__ out_t2,
             int write_vt, int write_t2)
{
    __shared__ unsigned short s_sol[CTPB * SOLSTRIDE];
    __shared__ int            s_lnk[CTPB * 101];

    const int lane = threadIdx.x;            // == lane, one warp per block
    const int b    = blockIdx.x * CTPB + lane;

    // dtype sniff: int64 viewed as int32 has zero odd words; an int32 row
    // has exactly one zero, so words 1,3,5 cannot all be zero.
    const bool is_i64 = (sol32[1] == 0) & (sol32[3] == 0) & (sol32[5] == 0);

    // cooperative staged load of 32 solution rows (u16: values <= 200)
    {
        const int b0 = blockIdx.x * CTPB;
        for (int e = lane; e < CTPB * SS; e += CTPB) {
            const int t = e / SS, p = e - t * SS;
            const int v = is_i64 ? sol32[2 * ((b0 + t) * SS + p)]
                                 : sol32[(b0 + t) * SS + p];
            s_sol[t * SOLSTRIDE + p] = (unsigned short)v;
        }
    }
    __syncwarp();

#define LNK(p) s_lnk[(p) * CTPB + lane]

    unsigned m0 = 0, m1m = 0, m2m = 0, m3m = 0;   // in-list bitmask, slots 1..100
    int head = 0, second = 0, pre = 0;
    const int base = b * SS;
    const unsigned short* mysol = s_sol + lane * SOLSTRIDE;

    for (int i = 0; i < SS; i++) {
        const int cur = (int)mysol[pre];
        pre = cur;
        const int vt = i + 1;

        if (cur != 0) {
            if (cur <= HALF) {
                // ---- push p = cur ----
                const int p = cur;
                const int w = p >> 5;
                const unsigned bit = 1u << (p & 31);
                if      (w == 0) m0  |= bit;
                else if (w == 1) m1m |= bit;
                else if (w == 2) m2m |= bit;
                else             m3m |= bit;
                const int oh = head;
                LNK(p)  = oh | (255 << 8);                    // next=oh, prev=NONE
                LNK(oh) = (LNK(oh) & 255) | (p << 8);         // prev[oh] = p
                second  = oh;
                head    = p;
            } else {
                // ---- pop p = cur - HALF (only if in list) ----
                const int p = cur - HALF;
                const int w = p >> 5;
                const unsigned bit = 1u << (p & 31);
                const unsigned mw = (w == 0) ? m0 : (w == 1) ? m1m
                                 : (w == 2) ? m2m : m3m;
                if (mw & bit) {
                    if      (w == 0) m0  &= ~bit;
                    else if (w == 1) m1m &= ~bit;
                    else if (w == 2) m2m &= ~bit;
                    else             m3m &= ~bit;
                    const int ln = LNK(p);
                    const int nx = ln & 255, pv = ln >> 8;
                    if (pv == 255) {                 // p was head
                        head = nx;
                        if (nx != 0) {
                            const int lnx = LNK(nx);
                            LNK(nx) = (lnx & 255) | (255 << 8);  // prev[nx]=NONE
                            second  = lnx & 255;                 // next[nx]
                        }
                    } else {
                        LNK(pv) = (LNK(pv) & 0xFF00) | nx;       // next[pv]=nx
                        LNK(nx) = (LNK(nx) & 0x00FF) | (pv << 8);// prev[nx]=pv
                        if (pv == head) second = nx;
                    }
                }
            }
        }

        const int row = base + cur;
        g_visited[row] = vt;
        if (write_vt) out_vt[row] = (float)vt;
        if (write_t2) {
            const int i2 = (head == 0) ? 1 : second;
            out_t2[row] = make_float2((float)head, (float)i2);
        }
    }
#undef LNK
}

// ---------------------------------------------------------------------------
// Kernel 2: x_embedding = x @ W^T  and  pos_enc = pattern[visited % S].
// One warp per (b,s) row; one float4 of each output per thread. Pure BW.
// (identical to round-3 version: 81 us @ 57% DRAM)
// ---------------------------------------------------------------------------
__global__ void __launch_bounds__(256)
embed_kernel(const float2* __restrict__ x2,
             const float4* __restrict__ W4,
             const float4* __restrict__ patt4,
             float4* __restrict__ out_emb,
             float4* __restrict__ out_pos,
             int write_pos)
{
    const int gid = blockIdx.x * 256 + threadIdx.x;
    const int r   = gid >> 5;
    const int q   = gid & 31;

    const float2 xv  = __ldcs(&x2[r]);
    const float4 w01 = __ldg(&W4[2 * q]);
    const float4 w23 = __ldg(&W4[2 * q + 1]);

    float4 e;
    e.x = xv.x * w01.x + xv.y * w01.y;
    e.y = xv.x * w01.z + xv.y * w01.w;
    e.z = xv.x * w23.x + xv.y * w23.y;
    e.w = xv.x * w23.z + xv.y * w23.w;
    __stcs(&out_emb[r * 32 + q], e);

    if (write_pos) {
        const int vt = g_visited[r];                   // 1..201
        const int p  = (vt >= SS) ? (vt - SS) : vt;    // == vt % 201
        __stcs(&out_pos[r * 32 + q], __ldg(&patt4[p * 32 + q]));
    }
}

// ---------------------------------------------------------------------------
extern "C" void kernel_launch(void* const* d_in, const int* in_sizes, int n_in,
                              void* d_out, int out_size)
{
    const float* x   = nullptr;
    const int*   sol = nullptr;
    const float* W   = nullptr;
    const float* pat = nullptr;

    for (int i = 0; i < n_in; i++) {
        switch (in_sizes[i]) {
            case ROWS * 2: x   = (const float*)d_in[i]; break;  // x
            case ROWS:     sol = (const int*)  d_in[i]; break;  // solutions
            case 256:      W   = (const float*)d_in[i]; break;  // W
            case SS * DD:  pat = (const float*)d_in[i]; break;  // pattern
            default: break;
        }
    }

    float* out = (float*)d_out;

    const int write_pos = (out_size >= 2 * A_EL) ? 1 : 0;
    const int write_vt  = (out_size >= 2 * A_EL + ROWS) ? 1 : 0;
    const int write_t2  = (out_size >= 2 * A_EL + 3 * ROWS) ? 1 : 0;

    float*  out_vt = out + (size_t)2 * A_EL;
    float2* out_t2 = (float2*)(out + (size_t)2 * A_EL + ROWS);

    chase_kernel<<<BB / CTPB, CTPB>>>(sol, out_vt, out_t2, write_vt, write_t2);

    embed_kernel<<<EMB_BLOCKS, 256>>>(
        (const float2*)x, (const float4*)W, (const float4*)pat,
        (float4*)out, (float4*)(out + (size_t)A_EL), write_pos);
}

// round 6
// speedup vs baseline: 1.6609x; 1.6609x over previous
#include <cuda_runtime.h>
#include <cstdint>

#define BB    2048
#define SS    201
#define HALF  100
#define DD    128
#define ROWS  (BB*SS)          /* 411648 */
#define A_EL  (ROWS*DD)        /* 52697088 : elems of x_embedding (== pos_enc) */

#define EMB_BLOCKS ((ROWS*32)/256)   /* 51456 */

// scratch: visited_time as int32 for the gather (static device array: allowed)
__device__ int g_visited[ROWS];

// ---------------------------------------------------------------------------
// Kernel 1: warp-per-batch pointer chase + O(1) incremental top-2.
//
// key(slot) = t*512 + 511 - slot  (push at time t) ; popped/-0.01 -> -1-slot ;
// slot0(0.0) -> 511. All keys distinct; slot = 511 - (key & 511) for both
// signs. max/2nd-max keys == lax.top_k(stacks,2) incl. tie-breaks.
//
// push: new key > all, displaced key <= m2 (or is m2)  => m2=m1; m1=nk (ALU)
// pop p: if p not in {s1,s2} the top-2 is provably unchanged (old key < m2,
//        new key -1-p < m2 by distinctness)            => zero work
//        else rare full recompute: per-lane top2 of 4 keys + 2x reduce_max
// cur is warp-uniform => no divergence; chain = 1 broadcast LDS + ALU.
// ---------------------------------------------------------------------------
__global__ void __launch_bounds__(128)
chase_kernel(const int* __restrict__ sol32,
             float*  __restrict__ out_vt,
             float2* __restrict__ out_t2,
             int write_vt, int write_t2)
{
    __shared__ int s_sol[4][SS + 7];
    const int warp = threadIdx.x >> 5;
    const int lane = threadIdx.x & 31;
    const int b    = blockIdx.x * 4 + warp;

    // dtype sniff: int64 viewed as int32 has zero odd words; an int32 row
    // has exactly one zero, so words 1,3,5 cannot all be zero.
    const bool is_i64 = (sol32[1] == 0) & (sol32[3] == 0) & (sol32[5] == 0);
    if (is_i64) {
        const int* p = sol32 + 2 * b * SS;
        for (int i = lane; i < SS; i += 32) s_sol[warp][i] = p[2 * i];
    } else {
        const int* p = sol32 + b * SS;
        for (int i = lane; i < SS; i += 32) s_sol[warp][i] = p[i];
    }
    __syncwarp();

    const int NEG = (-2147483647 - 1);
    // lane owns slots lane, lane+32, lane+64, lane+96 (valid while <= 100)
    int key0 = (lane == 0) ? 511 : (-1 - lane);
    int key1 = -1 - (lane + 32);
    int key2 = -1 - (lane + 64);
    int key3 = (lane + 96 <= HALF) ? (-1 - (lane + 96)) : NEG;

    int m1 = 511;   // slot 0 (value 0.0)
    int m2 = -2;    // slot 1 (value -0.01)

    int pre = 0;
    const int base = b * SS;

    for (int i = 0; i < SS; i++) {
        const int cur = s_sol[warp][pre];   // warp-uniform broadcast
        pre = cur;
        const int vt = i + 1;

        if (cur != 0) {
            if (cur <= HALF) {
                // ---- push ----
                const int pos = cur;
                const int nk  = vt * 512 + 511 - pos;
                if ((pos & 31) == lane) {
                    const int k = pos >> 5;
                    if      (k == 0) key0 = nk;
                    else if (k == 1) key1 = nk;
                    else if (k == 2) key2 = nk;
                    else             key3 = nk;
                }
                m2 = m1;
                m1 = nk;
            } else {
                // ---- pop ----
                const int pos  = cur - HALF;
                const int knew = -1 - pos;
                const int s1   = 511 - (m1 & 511);
                const int s2   = 511 - (m2 & 511);
                if ((pos & 31) == lane) {
                    const int k = pos >> 5;
                    if      (k == 0) key0 = knew;
                    else if (k == 1) key1 = knew;
                    else if (k == 2) key2 = knew;
                    else             key3 = knew;
                }
                if (pos == s1 || pos == s2) {
                    // rare: popped a top-2 holder -> full recompute
                    int a  = max(key0, key1), bl = min(key0, key1);
                    int c  = max(key2, key3), dl = min(key2, key3);
                    int l1 = max(a, c);
                    int l2 = max(min(a, c), max(bl, dl));
                    const int M1   = __reduce_max_sync(0xffffffffu, l1);
                    const int cand = (l1 == M1) ? l2 : l1;   // keys distinct
                    m2 = __reduce_max_sync(0xffffffffu, cand);
                    m1 = M1;
                }
                // else: top-2 provably unchanged
            }
        }
        // cur == 0: stacks[0] rewritten with itself -> state unchanged

        if (lane == 0) {
            const int row = base + cur;
            g_visited[row] = vt;
            if (write_vt) out_vt[row] = (float)vt;
            if (write_t2) out_t2[row] = make_float2(
                              (float)(511 - (m1 & 511)),
                              (float)(511 - (m2 & 511)));
        }
    }
}

// ---------------------------------------------------------------------------
// Kernel 2: x_embedding = x @ W^T  and  pos_enc = pattern[visited % S].
// One warp per (b,s) row; one float4 of each output per thread. Pure BW.
// (proven: ~79-81 us @ ~58% DRAM)
// ---------------------------------------------------------------------------
__global__ void __launch_bounds__(256)
embed_kernel(const float2* __restrict__ x2,
             const float4* __restrict__ W4,
             const float4* __restrict__ patt4,
             float4* __restrict__ out_emb,
             float4* __restrict__ out_pos,
             int write_pos)
{
    const int gid = blockIdx.x * 256 + threadIdx.x;
    const int r   = gid >> 5;
    const int q   = gid & 31;

    const float2 xv  = __ldcs(&x2[r]);
    const float4 w01 = __ldg(&W4[2 * q]);
    const float4 w23 = __ldg(&W4[2 * q + 1]);

    float4 e;
    e.x = xv.x * w01.x + xv.y * w01.y;
    e.y = xv.x * w01.z + xv.y * w01.w;
    e.z = xv.x * w23.x + xv.y * w23.y;
    e.w = xv.x * w23.z + xv.y * w23.w;
    __stcs(&out_emb[r * 32 + q], e);

    if (write_pos) {
        const int vt = g_visited[r];                   // 1..201
        const int p  = (vt >= SS) ? (vt - SS) : vt;    // == vt % 201
        __stcs(&out_pos[r * 32 + q], __ldg(&patt4[p * 32 + q]));
    }
}

// ---------------------------------------------------------------------------
extern "C" void kernel_launch(void* const* d_in, const int* in_sizes, int n_in,
                              void* d_out, int out_size)
{
    const float* x   = nullptr;
    const int*   sol = nullptr;
    const float* W   = nullptr;
    const float* pat = nullptr;

    for (int i = 0; i < n_in; i++) {
        switch (in_sizes[i]) {
            case ROWS * 2: x   = (const float*)d_in[i]; break;  // x
            case ROWS:     sol = (const int*)  d_in[i]; break;  // solutions
            case 256:      W   = (const float*)d_in[i]; break;  // W
            case SS * DD:  pat = (const float*)d_in[i]; break;  // pattern
            default: break;
        }
    }

    float* out = (float*)d_out;

    const int write_pos = (out_size >= 2 * A_EL) ? 1 : 0;
    const int write_vt  = (out_size >= 2 * A_EL + ROWS) ? 1 : 0;
    const int write_t2  = (out_size >= 2 * A_EL + 3 * ROWS) ? 1 : 0;

    float*  out_vt = out + (size_t)2 * A_EL;
    float2* out_t2 = (float2*)(out + (size_t)2 * A_EL + ROWS);

    chase_kernel<<<BB / 4, 128>>>(sol, out_vt, out_t2, write_vt, write_t2);

    embed_kernel<<<EMB_BLOCKS, 256>>>(
        (const float2*)x, (const float4*)W, (const float4*)pat,
        (float4*)out, (float4*)(out + (size_t)A_EL), write_pos);
}

// round 7
// speedup vs baseline: 1.6971x; 1.0218x over previous
#include <cuda_runtime.h>
#include <cstdint>

#define BB    2048
#define SS    201
#define HALF  100
#define DD    128
#define ROWS  (BB*SS)          /* 411648 */
#define A_EL  (ROWS*DD)        /* 52697088 : elems of x_embedding (== pos_enc) */

#define EMB_BLOCKS ((ROWS*32)/256)   /* 51456 */

// scratch: visited_time as int32 for the gather (static device array: allowed)
__device__ int g_visited[ROWS];

// ---------------------------------------------------------------------------
// Kernel 1: warp-per-batch pointer chase + O(1) incremental top-2,
// FLATTENED: one straight-line predicated iteration, single rare branch.
//
// key(slot) = t*512 + 511 - slot  (push at time t) ; popped/-0.01 -> -1-slot ;
// slot0(0.0) -> 511. All keys distinct; slot = 511 - (key & 511) for both
// signs (two's complement). max/2nd-max == lax.top_k(stacks,2) w/ tie-breaks.
//
// push: nk > all keys, displaced key < old m1        => m2=m1; m1=nk  (SELs)
// pop p: top-2 unchanged unless p is s1 or s2        => rare recompute only
// cur is warp-uniform => no divergence; chain = 1 broadcast LDS + SELs.
// ---------------------------------------------------------------------------
__global__ void __launch_bounds__(128)
chase_kernel(const int* __restrict__ sol32,
             float*  __restrict__ out_vt,
             float2* __restrict__ out_t2,
             int write_vt, int write_t2)
{
    __shared__ int s_sol[4][SS + 7];
    const int warp = threadIdx.x >> 5;
    const int lane = threadIdx.x & 31;
    const int b    = blockIdx.x * 4 + warp;

    // dtype sniff: int64 viewed as int32 has zero odd words; an int32 row
    // has exactly one zero, so words 1,3,5 cannot all be zero.
    const bool is_i64 = (sol32[1] == 0) & (sol32[3] == 0) & (sol32[5] == 0);
    if (is_i64) {
        const int* p = sol32 + 2 * b * SS;
        for (int i = lane; i < SS; i += 32) s_sol[warp][i] = p[2 * i];
    } else {
        const int* p = sol32 + b * SS;
        for (int i = lane; i < SS; i += 32) s_sol[warp][i] = p[i];
    }
    __syncwarp();

    const int NEG = (-2147483647 - 1);
    // lane owns slots lane, lane+32, lane+64, lane+96 (valid while <= 100)
    int key0 = (lane == 0) ? 511 : (-1 - lane);
    int key1 = -1 - (lane + 32);
    int key2 = -1 - (lane + 64);
    int key3 = (lane + 96 <= HALF) ? (-1 - (lane + 96)) : NEG;

    int m1 = 511;   // slot 0 (value 0.0)
    int m2 = -2;    // slot 1 (value -0.01)

    int pre = 0;
    const int base = b * SS;
    const bool wv = (write_vt != 0), wt = (write_t2 != 0);

    #pragma unroll 3
    for (int i = 0; i < SS; i++) {
        const int cur = s_sol[warp][pre];   // warp-uniform broadcast
        pre = cur;
        const int vt = i + 1;

        const bool act  = (cur != 0);
        const bool push = act & (cur <= HALF);
        const bool pop  = act & (cur > HALF);

        const int pos = pop ? (cur - HALF) : cur;
        const int nk  = push ? (vt * 512 + 511 - pos) : (-1 - pos);

        // key-register update: 4 independent selects
        const bool mine = act & ((pos & 31) == lane);
        const int  k    = pos >> 5;
        key0 = (mine & (k == 0)) ? nk : key0;
        key1 = (mine & (k == 1)) ? nk : key1;
        key2 = (mine & (k == 2)) ? nk : key2;
        key3 = (mine & (k == 3)) ? nk : key3;

        // top-2 fast path: 2 selects
        m2 = push ? m1 : m2;
        m1 = push ? nk : m1;

        // rare slow path: popped a top-2 holder (warp-uniform branch)
        const int s1 = 511 - (m1 & 511);
        const int s2 = 511 - (m2 & 511);
        if (pop & ((pos == s1) | (pos == s2))) {
            int a  = max(key0, key1), bl = min(key0, key1);
            int c  = max(key2, key3), dl = min(key2, key3);
            int l1 = max(a, c);
            int l2 = max(min(a, c), max(bl, dl));
            const int M1   = __reduce_max_sync(0xffffffffu, l1);
            const int cand = (l1 == M1) ? l2 : l1;   // keys distinct
            m2 = __reduce_max_sync(0xffffffffu, cand);
            m1 = M1;
        }

        // predicated per-row outputs (lane 0 only)
        const int row = base + cur;
        if (lane == 0)       g_visited[row] = vt;
        if (lane == 0 && wv) out_vt[row]    = (float)vt;
        if (lane == 0 && wt) out_t2[row]    = make_float2(
                                  (float)(511 - (m1 & 511)),
                                  (float)(511 - (m2 & 511)));
    }
}

// ---------------------------------------------------------------------------
// Kernel 2: x_embedding = x @ W^T  and  pos_enc = pattern[visited % S].
// One warp per (b,s) row; one float4 of each output per thread. Pure BW.
// (proven: ~79 us @ ~58% DRAM)
// ---------------------------------------------------------------------------
__global__ void __launch_bounds__(256)
embed_kernel(const float2* __restrict__ x2,
             const float4* __restrict__ W4,
             const float4* __restrict__ patt4,
             float4* __restrict__ out_emb,
             float4* __restrict__ out_pos,
             int write_pos)
{
    const int gid = blockIdx.x * 256 + threadIdx.x;
    const int r   = gid >> 5;
    const int q   = gid & 31;

    const float2 xv  = __ldcs(&x2[r]);
    const float4 w01 = __ldg(&W4[2 * q]);
    const float4 w23 = __ldg(&W4[2 * q + 1]);

    float4 e;
    e.x = xv.x * w01.x + xv.y * w01.y;
    e.y = xv.x * w01.z + xv.y * w01.w;
    e.z = xv.x * w23.x + xv.y * w23.y;
    e.w = xv.x * w23.z + xv.y * w23.w;
    __stcs(&out_emb[r * 32 + q], e);

    if (write_pos) {
        const int vt = g_visited[r];                   // 1..201
        const int p  = (vt >= SS) ? (vt - SS) : vt;    // == vt % 201
        __stcs(&out_pos[r * 32 + q], __ldg(&patt4[p * 32 + q]));
    }
}

// ---------------------------------------------------------------------------
extern "C" void kernel_launch(void* const* d_in, const int* in_sizes, int n_in,
                              void* d_out, int out_size)
{
    const float* x   = nullptr;
    const int*   sol = nullptr;
    const float* W   = nullptr;
    const float* pat = nullptr;

    for (int i = 0; i < n_in; i++) {
        switch (in_sizes[i]) {
            case ROWS * 2: x   = (const float*)d_in[i]; break;  // x
            case ROWS:     sol = (const int*)  d_in[i]; break;  // solutions
            case 256:      W   = (const float*)d_in[i]; break;  // W
            case SS * DD:  pat = (const float*)d_in[i]; break;  // pattern
            default: break;
        }
    }

    float* out = (float*)d_out;

    const int write_pos = (out_size >= 2 * A_EL) ? 1 : 0;
    const int write_vt  = (out_size >= 2 * A_EL + ROWS) ? 1 : 0;
    const int write_t2  = (out_size >= 2 * A_EL + 3 * ROWS) ? 1 : 0;

    float*  out_vt = out + (size_t)2 * A_EL;
    float2* out_t2 = (float2*)(out + (size_t)2 * A_EL + ROWS);

    chase_kernel<<<BB / 4, 128>>>(sol, out_vt, out_t2, write_vt, write_t2);

    embed_kernel<<<EMB_BLOCKS, 256>>>(
        (const float2*)x, (const float4*)W, (const float4*)pat,
        (float4*)out, (float4*)(out + (size_t)A_EL), write_pos);
}

// round 8
// speedup vs baseline: 1.9339x; 1.1395x over previous
#include <cuda_runtime.h>
#include <cstdint>

#define BB    2048
#define SS    201
#define HALF  100
#define DD    128
#define ROWS  (BB*SS)          /* 411648 */
#define A_EL  (ROWS*DD)        /* 52697088 : elems of x_embedding (== pos_enc) */

#define RPB   16                      /* rows per embed block */
#define EMB_BLOCKS (ROWS/RPB)         /* 25728 */

// scratch: visited_time as int32 for the gather (static device array: allowed)
__device__ int g_visited[ROWS];

// ---------------------------------------------------------------------------
// Kernel 1: warp-per-batch pointer chase + O(1) incremental top-2.
// Issue-diet version: slot keys live in SMEM (one predicated STS/iter)
// instead of 4 per-lane registers (12+ instr/iter of select logic).
//
// key(slot) = t*512 + 511 - slot (push at t); popped/-0.01 -> -1-slot;
// slot0(0.0) -> 511. Keys distinct; slot = 511 - (key & 511) for both signs.
// push: nk > all keys, displaced key <= m2      => m2=m1; m1=nk   (2 SELs)
// pop p: top-2 unchanged unless p in {s1,s2}    => rare recompute only
// ---------------------------------------------------------------------------
__global__ void __launch_bounds__(128)
chase_kernel(const int* __restrict__ sol32,
             float*  __restrict__ out_vt,
             float2* __restrict__ out_t2,
             int write_vt, int write_t2)
{
    __shared__ int s_sol[4][SS + 7];
    __shared__ int s_keys[4][128];

    const int warp = threadIdx.x >> 5;
    const int lane = threadIdx.x & 31;
    const int b    = blockIdx.x * 4 + warp;

    // dtype sniff: int64 viewed as int32 has zero odd words; an int32 row
    // has exactly one zero, so words 1,3,5 cannot all be zero.
    const bool is_i64 = (sol32[1] == 0) & (sol32[3] == 0) & (sol32[5] == 0);
    if (is_i64) {
        const int* p = sol32 + 2 * b * SS;
        for (int i = lane; i < SS; i += 32) s_sol[warp][i] = p[2 * i];
    } else {
        const int* p = sol32 + b * SS;
        for (int i = lane; i < SS; i += 32) s_sol[warp][i] = p[i];
    }
    // init keys: slot0=511 (value 0.0); slots 1..100 = -1-s (-0.01);
    // 101..127 = -inf sentinels
    #pragma unroll
    for (int i = lane; i < 128; i += 32)
        s_keys[warp][i] = (i == 0) ? 511
                        : (i <= HALF) ? (-1 - i) : (-2147483647 - 1);
    __syncwarp();

    int m1 = 511;   // slot 0 (0.0)
    int m2 = -2;    // slot 1 (-0.01)

    int pre = 0;
    const int base = b * SS;
    const bool wv = (write_vt != 0), wt = (write_t2 != 0);

    #pragma unroll 4
    for (int i = 0; i < SS; i++) {
        const int cur = s_sol[warp][pre];   // warp-uniform broadcast
        pre = cur;
        const int vt = i + 1;

        const bool act  = (cur != 0);
        const bool push = act & (cur <= HALF);
        const bool pop  = (cur > HALF);

        const int pos = pop ? (cur - HALF) : cur;
        const int nk  = push ? (vt * 512 + 511 - pos) : (-1 - pos);

        if (act && lane == 0) s_keys[warp][pos] = nk;   // 1 predicated STS

        m2 = push ? m1 : m2;
        m1 = push ? nk : m1;

        const int s1 = 511 - (m1 & 511);
        const int s2 = 511 - (m2 & 511);
        if (pop && ((pos == s1) | (pos == s2))) {
            // rare (~10/201): popped a top-2 holder -> full recompute
            __syncwarp();                    // make lane0's STS visible
            const int k0 = s_keys[warp][lane];
            const int k1 = s_keys[warp][lane + 32];
            const int k2 = s_keys[warp][lane + 64];
            const int k3 = s_keys[warp][lane + 96];
            int a  = max(k0, k1), bl = min(k0, k1);
            int c  = max(k2, k3), dl = min(k2, k3);
            int l1 = max(a, c);
            int l2 = max(min(a, c), max(bl, dl));
            const int M1   = __reduce_max_sync(0xffffffffu, l1);
            const int cand = (l1 == M1) ? l2 : l1;   // keys distinct
            m2 = __reduce_max_sync(0xffffffffu, cand);
            m1 = M1;
        }

        const int row = base + cur;
        if (lane == 0)       g_visited[row] = vt;
        if (lane == 0 && wv) out_vt[row]    = (float)vt;
        if (lane == 0 && wt) out_t2[row]    = make_float2(
                                  (float)(511 - (m1 & 511)),
                                  (float)(511 - (m2 & 511)));
    }
}

// ---------------------------------------------------------------------------
// Kernel 2: x_embedding = x @ W^T and pos_enc = pattern[visited % S].
// TMA-store version: compute 16 rows into SMEM (cheap STS.128), drain with
// cp.async.bulk (UBLKCP) -> the 420 MB write stream bypasses L1tex/STG-issue.
// ---------------------------------------------------------------------------
__global__ void __launch_bounds__(256)
embed_kernel(const float2* __restrict__ x2,
             const float4* __restrict__ W4,
             const float4* __restrict__ patt4,
             float*  __restrict__ out_emb,
             float*  __restrict__ out_pos,
             int write_pos)
{
    __shared__ __align__(16) float s_emb[RPB * DD];   // 8 KB
    __shared__ __align__(16) float s_pos[RPB * DD];   // 8 KB

    const int warp = threadIdx.x >> 5;
    const int lane = threadIdx.x & 31;
    const int r0   = blockIdx.x * RPB;

    const float4 w01 = __ldg(&W4[2 * lane]);
    const float4 w23 = __ldg(&W4[2 * lane + 1]);

    #pragma unroll
    for (int rr = warp; rr < RPB; rr += 8) {
        const int r = r0 + rr;
        const float2 xv = __ldcs(&x2[r]);

        float4 e;
        e.x = xv.x * w01.x + xv.y * w01.y;
        e.y = xv.x * w01.z + xv.y * w01.w;
        e.z = xv.x * w23.x + xv.y * w23.y;
        e.w = xv.x * w23.z + xv.y * w23.w;
        reinterpret_cast<float4*>(s_emb)[rr * 32 + lane] = e;

        if (write_pos) {
            const int vt = g_visited[r];                  // 1..201 (uniform)
            const int p  = (vt >= SS) ? (vt - SS) : vt;   // == vt % 201
            reinterpret_cast<float4*>(s_pos)[rr * 32 + lane] =
                __ldg(&patt4[p * 32 + lane]);
        }
    }
    __syncthreads();

    if (threadIdx.x == 0) {
        asm volatile("fence.proxy.async.shared::cta;" ::: "memory");
        const unsigned se = (unsigned)__cvta_generic_to_shared(s_emb);
        const unsigned sp = (unsigned)__cvta_generic_to_shared(s_pos);
        asm volatile(
            "cp.async.bulk.global.shared::cta.bulk_group [%0], [%1], %2;"
            :: "l"(out_emb + (size_t)r0 * DD), "r"(se), "r"(RPB * DD * 4)
            : "memory");
        if (write_pos)
            asm volatile(
                "cp.async.bulk.global.shared::cta.bulk_group [%0], [%1], %2;"
                :: "l"(out_pos + (size_t)r0 * DD), "r"(sp), "r"(RPB * DD * 4)
                : "memory");
        asm volatile("cp.async.bulk.commit_group;" ::: "memory");
        asm volatile("cp.async.bulk.wait_group 0;" ::: "memory");
    }
}

// ---------------------------------------------------------------------------
extern "C" void kernel_launch(void* const* d_in, const int* in_sizes, int n_in,
                              void* d_out, int out_size)
{
    const float* x   = nullptr;
    const int*   sol = nullptr;
    const float* W   = nullptr;
    const float* pat = nullptr;

    for (int i = 0; i < n_in; i++) {
        switch (in_sizes[i]) {
            case ROWS * 2: x   = (const float*)d_in[i]; break;  // x
            case ROWS:     sol = (const int*)  d_in[i]; break;  // solutions
            case 256:      W   = (const float*)d_in[i]; break;  // W
            case SS * DD:  pat = (const float*)d_in[i]; break;  // pattern
            default: break;
        }
    }

    float* out = (float*)d_out;

    const int write_pos = (out_size >= 2 * A_EL) ? 1 : 0;
    const int write_vt  = (out_size >= 2 * A_EL + ROWS) ? 1 : 0;
    const int write_t2  = (out_size >= 2 * A_EL + 3 * ROWS) ? 1 : 0;

    float*  out_vt = out + (size_t)2 * A_EL;
    float2* out_t2 = (float2*)(out + (size_t)2 * A_EL + ROWS);

    chase_kernel<<<BB / 4, 128>>>(sol, out_vt, out_t2, write_vt, write_t2);

    embed_kernel<<<EMB_BLOCKS, 256>>>(
        (const float2*)x, (const float4*)W, (const float4*)pat,
        out, out + (size_t)A_EL, write_pos);
}

// round 9
// speedup vs baseline: 2.0958x; 1.0837x over previous
#include <cuda_runtime.h>
#include <cstdint>

#define BB    2048
#define SS    201
#define HALF  100
#define DD    128
#define ROWS  (BB*SS)          /* 411648 */
#define A_EL  (ROWS*DD)        /* 52697088 : elems of x_embedding (== pos_enc) */

#define RPB   16                      /* rows per embed block */
#define EMB_BLOCKS (ROWS/RPB)         /* 25728 */
#define WPB   4                       /* warps per chase block */

// scratch: visited_time as int32 for the gather (static device array: allowed)
__device__ int g_visited[ROWS];

// ---------------------------------------------------------------------------
// Kernel 1: warp-per-batch chase, restructured:
//  (a) pointer doubling builds order[k] = sol^k(0) in 8 lane-parallel phases
//      -> serial pass has NO loop-carried LDS chain
//  (b) branch-free serial top-2 pass (SELs + unconditional STS), packed
//      results buffered in SMEM
//  (c) lane-parallel scatter epilogue for visited/vt/top2
//
// key(slot) = t*512 + 511 - slot (push at t); popped/-0.01 -> -1-slot;
// slot0(0.0) -> 511. Keys distinct; slot = 511 - (key & 511) for both signs.
// push: nk > all keys, displaced key <= m2      => m2=m1; m1=nk   (2 SELs)
// pop p: top-2 unchanged unless p in {s1,s2}    => rare uniform recompute
// ---------------------------------------------------------------------------
__global__ void __launch_bounds__(128)
chase_kernel(const int* __restrict__ sol32,
             float*  __restrict__ out_vt,
             float2* __restrict__ out_t2,
             int write_vt, int write_t2)
{
    __shared__ int s_f   [WPB][256];
    __shared__ int s_g   [WPB][256];
    __shared__ int s_ord [WPB][208];
    __shared__ int s_keys[WPB][160];
    __shared__ int s_t2  [WPB][208];

    const int warp = threadIdx.x >> 5;
    const int lane = threadIdx.x & 31;
    const int b    = blockIdx.x * WPB + warp;

    // dtype sniff: int64 viewed as int32 has zero odd words; an int32 row
    // has exactly one zero, so words 1,3,5 cannot all be zero.
    const bool is_i64 = (sol32[1] == 0) & (sol32[3] == 0) & (sol32[5] == 0);
    if (is_i64) {
        const int* p = sol32 + 2 * b * SS;
        for (int i = lane; i < SS; i += 32) s_f[warp][i] = p[2 * i];
    } else {
        const int* p = sol32 + b * SS;
        for (int i = lane; i < SS; i += 32) s_f[warp][i] = p[i];
    }
    // keys: slot0=511 (0.0); 1..100 = -1-s (-0.01); 101..159 sentinel/dummy
    for (int i = lane; i < 160; i += 32)
        s_keys[warp][i] = (i == 0) ? 511
                        : (i <= HALF) ? (-1 - i) : (-2147483647 - 1);
    if (lane == 0) { s_ord[warp][0] = 0; s_ord[warp][SS] = 0; }
    __syncwarp();

    // ---- pointer doubling: ord[k] = sol^k(0), k = 0..200 ----
    {
        int* F = s_f[warp];
        int* G = s_g[warp];
        int len = 1;
        while (len < SS) {
            const int hi = (2 * len < SS) ? 2 * len : SS;
            for (int k = len + lane; k < hi; k += 32)
                s_ord[warp][k] = F[s_ord[warp][k - len]];
            if (hi < SS) {                       // F = F o F
                for (int i = lane; i < SS; i += 32) G[i] = F[F[i]];
                int* t = F; F = G; G = t;
            }
            len = hi;
            __syncwarp();
        }
    }

    // ---- serial top-2 pass (branch-free fast path) ----
    int m1 = 511;   // slot 0 (0.0)
    int m2 = -2;    // slot 1 (-0.01)

    #pragma unroll 8
    for (int i = 0; i < SS; i++) {
        const int cur = s_ord[warp][i + 1];      // independent broadcast LDS
        const int vt  = i + 1;

        const bool act  = (cur != 0);
        const bool push = act & (cur <= HALF);
        const bool pop  = (cur > HALF);

        const int pos = pop ? (cur - HALF) : cur;
        const int nk  = push ? (vt * 512 + 511 - pos) : (-1 - pos);

        // unconditional STS: lane 0 writes the real slot, others a dummy bank
        const int widx = (act & (lane == 0)) ? pos : (128 + lane);
        s_keys[warp][widx] = nk;

        m2 = push ? m1 : m2;
        m1 = push ? nk : m1;

        const int s1 = 511 - (m1 & 511);
        const int s2 = 511 - (m2 & 511);
        if (pop && ((pos == s1) | (pos == s2))) {
            // rare, warp-uniform: popped a top-2 holder -> full recompute
            __syncwarp();
            const int k0 = s_keys[warp][lane];
            const int k1 = s_keys[warp][lane + 32];
            const int k2 = s_keys[warp][lane + 64];
            const int k3 = s_keys[warp][lane + 96];
            int a  = max(k0, k1), bl = min(k0, k1);
            int c  = max(k2, k3), dl = min(k2, k3);
            int l1 = max(a, c);
            int l2 = max(min(a, c), max(bl, dl));
            const int M1   = __reduce_max_sync(0xffffffffu, l1);
            const int cand = (l1 == M1) ? l2 : l1;   // keys distinct
            m2 = __reduce_max_sync(0xffffffffu, cand);
            m1 = M1;
        }

        if (lane == 0)
            s_t2[warp][i] = ((511 - (m1 & 511)) << 8) | (511 - (m2 & 511));
    }
    __syncwarp();

    // ---- lane-parallel scatter epilogue ----
    const int  base = b * SS;
    const bool wv = (write_vt != 0), wt = (write_t2 != 0);
    for (int k = 1 + lane; k <= SS; k += 32) {
        const int node = (k == SS) ? 0 : s_ord[warp][k];
        g_visited[base + node] = k;
        if (wv) out_vt[base + node] = (float)k;
        if (wt) {
            const int p2 = s_t2[warp][k - 1];
            out_t2[base + node] = make_float2((float)(p2 >> 8),
                                              (float)(p2 & 255));
        }
    }
}

// ---------------------------------------------------------------------------
// Kernel 2: x_embedding = x @ W^T and pos_enc = pattern[visited % S].
// Compute 16 rows into SMEM (cheap STS.128), drain with cp.async.bulk:
// the 420 MB write stream bypasses L1tex/STG-issue. (proven: 64.4 us @ 72%)
// ---------------------------------------------------------------------------
__global__ void __launch_bounds__(256)
embed_kernel(const float2* __restrict__ x2,
             const float4* __restrict__ W4,
             const float4* __restrict__ patt4,
             float*  __restrict__ out_emb,
             float*  __restrict__ out_pos,
             int write_pos)
{
    __shared__ __align__(16) float s_emb[RPB * DD];   // 8 KB
    __shared__ __align__(16) float s_pos[RPB * DD];   // 8 KB

    const int warp = threadIdx.x >> 5;
    const int lane = threadIdx.x & 31;
    const int r0   = blockIdx.x * RPB;

    const float4 w01 = __ldg(&W4[2 * lane]);
    const float4 w23 = __ldg(&W4[2 * lane + 1]);

    #pragma unroll
    for (int rr = warp; rr < RPB; rr += 8) {
        const int r = r0 + rr;
        const float2 xv = __ldcs(&x2[r]);

        float4 e;
        e.x = xv.x * w01.x + xv.y * w01.y;
        e.y = xv.x * w01.z + xv.y * w01.w;
        e.z = xv.x * w23.x + xv.y * w23.y;
        e.w = xv.x * w23.z + xv.y * w23.w;
        reinterpret_cast<float4*>(s_emb)[rr * 32 + lane] = e;

        if (write_pos) {
            const int vt = g_visited[r];                  // 1..201 (uniform)
            const int p  = (vt >= SS) ? (vt - SS) : vt;   // == vt % 201
            reinterpret_cast<float4*>(s_pos)[rr * 32 + lane] =
                __ldg(&patt4[p * 32 + lane]);
        }
    }
    __syncthreads();

    if (threadIdx.x == 0) {
        asm volatile("fence.proxy.async.shared::cta;" ::: "memory");
        const unsigned se = (unsigned)__cvta_generic_to_shared(s_emb);
        const unsigned sp = (unsigned)__cvta_generic_to_shared(s_pos);
        asm volatile(
            "cp.async.bulk.global.shared::cta.bulk_group [%0], [%1], %2;"
            :: "l"(out_emb + (size_t)r0 * DD), "r"(se), "r"(RPB * DD * 4)
            : "memory");
        if (write_pos)
            asm volatile(
                "cp.async.bulk.global.shared::cta.bulk_group [%0], [%1], %2;"
                :: "l"(out_pos + (size_t)r0 * DD), "r"(sp), "r"(RPB * DD * 4)
                : "memory");
        asm volatile("cp.async.bulk.commit_group;" ::: "memory");
        asm volatile("cp.async.bulk.wait_group 0;" ::: "memory");
    }
}

// ---------------------------------------------------------------------------
extern "C" void kernel_launch(void* const* d_in, const int* in_sizes, int n_in,
                              void* d_out, int out_size)
{
    const float* x   = nullptr;
    const int*   sol = nullptr;
    const float* W   = nullptr;
    const float* pat = nullptr;

    for (int i = 0; i < n_in; i++) {
        switch (in_sizes[i]) {
            case ROWS * 2: x   = (const float*)d_in[i]; break;  // x
            case ROWS:     sol = (const int*)  d_in[i]; break;  // solutions
            case 256:      W   = (const float*)d_in[i]; break;  // W
            case SS * DD:  pat = (const float*)d_in[i]; break;  // pattern
            default: break;
        }
    }

    float* out = (float*)d_out;

    const int write_pos = (out_size >= 2 * A_EL) ? 1 : 0;
    const int write_vt  = (out_size >= 2 * A_EL + ROWS) ? 1 : 0;
    const int write_t2  = (out_size >= 2 * A_EL + 3 * ROWS) ? 1 : 0;

    float*  out_vt = out + (size_t)2 * A_EL;
    float2* out_t2 = (float2*)(out + (size_t)2 * A_EL + ROWS);

    chase_kernel<<<BB / WPB, 128>>>(sol, out_vt, out_t2, write_vt, write_t2);

    embed_kernel<<<EMB_BLOCKS, 256>>>(
        (const float2*)x, (const float4*)W, (const float4*)pat,
        out, out + (size_t)A_EL, write_pos);
}

// round 10
// speedup vs baseline: 2.2092x; 1.0541x over previous
#include <cuda_runtime.h>
#include <cstdint>

#define BB    2048
#define SS    201
#define HALF  100
#define DD    128
#define ROWS  (BB*SS)          /* 411648 */
#define A_EL  (ROWS*DD)        /* 52697088 : elems of x_embedding (== pos_enc) */

#define RPB   16                      /* rows per embed tile */
#define EMB_BLOCKS (ROWS/RPB)         /* 25728 */
#define WPB   8                       /* warps per chase block (256 thr) */
#define CHASE_BLOCKS (BB/WPB)         /* 256 */

// scratch: visited_time as int32 for the gather (static device array: allowed)
__device__ int g_visited[ROWS];

// ---- shared-memory union: chase state vs emb tile buffers ----------------
struct ChaseSm {
    int f   [WPB][256];
    int g   [WPB][256];
    int ord [WPB][208];
    int keys[WPB][160];
    int t2  [WPB][208];
};
struct EmbSm {
    float emb[RPB * DD];
    float pos[RPB * DD];   // unused in k1, layout kept identical to k2
};
#define SMEM_BYTES (sizeof(ChaseSm) > sizeof(EmbSm) ? sizeof(ChaseSm) : sizeof(EmbSm))

// ---------------------------------------------------------------------------
// k1: fused [chase (bids 0..255)] || [emb-only tiles (bids 256..)].
// Chase: pointer doubling -> branch-free serial top-2 -> lane-parallel
// scatter (R9 logic, unchanged). Emb: compute 16 rows into SMEM, drain with
// cp.async.bulk (bypasses L1tex, so co-resident chase LDS stays unthrottled).
//
// key(slot) = t*512 + 511 - slot (push at t); popped/-0.01 -> -1-slot;
// slot0(0.0) -> 511. Keys distinct; slot = 511 - (key & 511) for both signs.
// push: nk > all keys, displaced key <= m2      => m2=m1; m1=nk   (2 SELs)
// pop p: top-2 unchanged unless p in {s1,s2}    => rare uniform recompute
// ---------------------------------------------------------------------------
__global__ void __launch_bounds__(256)
fused_kernel(const int*    __restrict__ sol32,
             const float2* __restrict__ x2,
             const float4* __restrict__ W4,
             float*  __restrict__ out_emb,
             float*  __restrict__ out_vt,
             float2* __restrict__ out_t2,
             int write_vt, int write_t2)
{
    __shared__ __align__(16) unsigned char smraw[SMEM_BYTES];

    if (blockIdx.x < CHASE_BLOCKS) {
        ChaseSm* sm = reinterpret_cast<ChaseSm*>(smraw);
        const int warp = threadIdx.x >> 5;
        const int lane = threadIdx.x & 31;
        const int b    = blockIdx.x * WPB + warp;

        // dtype sniff: int64 viewed as int32 has zero odd words; an int32 row
        // has exactly one zero, so words 1,3,5 cannot all be zero.
        const bool is_i64 = (sol32[1] == 0) & (sol32[3] == 0) & (sol32[5] == 0);
        if (is_i64) {
            const int* p = sol32 + 2 * b * SS;
            for (int i = lane; i < SS; i += 32) sm->f[warp][i] = p[2 * i];
        } else {
            const int* p = sol32 + b * SS;
            for (int i = lane; i < SS; i += 32) sm->f[warp][i] = p[i];
        }
        // keys: slot0=511 (0.0); 1..100 = -1-s (-0.01); 101..159 sentinel
        for (int i = lane; i < 160; i += 32)
            sm->keys[warp][i] = (i == 0) ? 511
                              : (i <= HALF) ? (-1 - i) : (-2147483647 - 1);
        if (lane == 0) { sm->ord[warp][0] = 0; sm->ord[warp][SS] = 0; }
        __syncwarp();

        // ---- pointer doubling: ord[k] = sol^k(0), k = 0..200 ----
        {
            int* F = sm->f[warp];
            int* G = sm->g[warp];
            int len = 1;
            while (len < SS) {
                const int hi = (2 * len < SS) ? 2 * len : SS;
                for (int k = len + lane; k < hi; k += 32)
                    sm->ord[warp][k] = F[sm->ord[warp][k - len]];
                if (hi < SS) {                   // F = F o F
                    for (int i = lane; i < SS; i += 32) G[i] = F[F[i]];
                    int* t = F; F = G; G = t;
                }
                len = hi;
                __syncwarp();
            }
        }

        // ---- serial top-2 pass (branch-free fast path) ----
        int m1 = 511;   // slot 0 (0.0)
        int m2 = -2;    // slot 1 (-0.01)

        #pragma unroll 8
        for (int i = 0; i < SS; i++) {
            const int cur = sm->ord[warp][i + 1];
            const int vt  = i + 1;

            const bool act  = (cur != 0);
            const bool push = act & (cur <= HALF);
            const bool pop  = (cur > HALF);

            const int pos = pop ? (cur - HALF) : cur;
            const int nk  = push ? (vt * 512 + 511 - pos) : (-1 - pos);

            const int widx = (act & (lane == 0)) ? pos : (128 + lane);
            sm->keys[warp][widx] = nk;

            m2 = push ? m1 : m2;
            m1 = push ? nk : m1;

            const int s1 = 511 - (m1 & 511);
            const int s2 = 511 - (m2 & 511);
            if (pop && ((pos == s1) | (pos == s2))) {
                // rare, warp-uniform: popped a top-2 holder -> recompute
                __syncwarp();
                const int k0 = sm->keys[warp][lane];
                const int k1 = sm->keys[warp][lane + 32];
                const int k2 = sm->keys[warp][lane + 64];
                const int k3 = sm->keys[warp][lane + 96];
                int a  = max(k0, k1), bl = min(k0, k1);
                int c  = max(k2, k3), dl = min(k2, k3);
                int l1 = max(a, c);
                int l2 = max(min(a, c), max(bl, dl));
                const int M1   = __reduce_max_sync(0xffffffffu, l1);
                const int cand = (l1 == M1) ? l2 : l1;   // keys distinct
                m2 = __reduce_max_sync(0xffffffffu, cand);
                m1 = M1;
            }

            if (lane == 0)
                sm->t2[warp][i] = ((511 - (m1 & 511)) << 8) | (511 - (m2 & 511));
        }
        __syncwarp();

        // ---- lane-parallel scatter epilogue ----
        const int  base = b * SS;
        const bool wv = (write_vt != 0), wt = (write_t2 != 0);
        for (int k = 1 + lane; k <= SS; k += 32) {
            const int node = (k == SS) ? 0 : sm->ord[warp][k];
            g_visited[base + node] = k;
            if (wv) out_vt[base + node] = (float)k;
            if (wt) {
                const int p2 = sm->t2[warp][k - 1];
                out_t2[base + node] = make_float2((float)(p2 >> 8),
                                                  (float)(p2 & 255));
            }
        }
    } else {
        // ---- emb-only tile: x_embedding = x @ W^T ----
        EmbSm* sm = reinterpret_cast<EmbSm*>(smraw);
        const int warp = threadIdx.x >> 5;
        const int lane = threadIdx.x & 31;
        const int r0   = (blockIdx.x - CHASE_BLOCKS) * RPB;

        const float4 w01 = __ldg(&W4[2 * lane]);
        const float4 w23 = __ldg(&W4[2 * lane + 1]);

        #pragma unroll
        for (int rr = warp; rr < RPB; rr += 8) {
            const float2 xv = __ldcs(&x2[r0 + rr]);
            float4 e;
            e.x = xv.x * w01.x + xv.y * w01.y;
            e.y = xv.x * w01.z + xv.y * w01.w;
            e.z = xv.x * w23.x + xv.y * w23.y;
            e.w = xv.x * w23.z + xv.y * w23.w;
            reinterpret_cast<float4*>(sm->emb)[rr * 32 + lane] = e;
        }
        __syncthreads();

        if (threadIdx.x == 0) {
            asm volatile("fence.proxy.async.shared::cta;" ::: "memory");
            const unsigned se = (unsigned)__cvta_generic_to_shared(sm->emb);
            asm volatile(
                "cp.async.bulk.global.shared::cta.bulk_group [%0], [%1], %2;"
                :: "l"(out_emb + (size_t)r0 * DD), "r"(se), "r"(RPB * DD * 4)
                : "memory");
            asm volatile("cp.async.bulk.commit_group;" ::: "memory");
            asm volatile("cp.async.bulk.wait_group 0;" ::: "memory");
        }
    }
}

// ---------------------------------------------------------------------------
// k2: pos_enc = pattern[visited % S]. Gather into SMEM, TMA bulk store.
// ---------------------------------------------------------------------------
__global__ void __launch_bounds__(256)
pos_kernel(const float4* __restrict__ patt4,
           float* __restrict__ out_pos)
{
    __shared__ __align__(16) float s_pos[RPB * DD];   // 8 KB

    const int warp = threadIdx.x >> 5;
    const int lane = threadIdx.x & 31;
    const int r0   = blockIdx.x * RPB;

    #pragma unroll
    for (int rr = warp; rr < RPB; rr += 8) {
        const int vt = g_visited[r0 + rr];            // 1..201 (warp-uniform)
        const int p  = (vt >= SS) ? (vt - SS) : vt;   // == vt % 201
        reinterpret_cast<float4*>(s_pos)[rr * 32 + lane] =
            __ldg(&patt4[p * 32 + lane]);
    }
    __syncthreads();

    if (threadIdx.x == 0) {
        asm volatile("fence.proxy.async.shared::cta;" ::: "memory");
        const unsigned sp = (unsigned)__cvta_generic_to_shared(s_pos);
        asm volatile(
            "cp.async.bulk.global.shared::cta.bulk_group [%0], [%1], %2;"
            :: "l"(out_pos + (size_t)r0 * DD), "r"(sp), "r"(RPB * DD * 4)
            : "memory");
        asm volatile("cp.async.bulk.commit_group;" ::: "memory");
        asm volatile("cp.async.bulk.wait_group 0;" ::: "memory");
    }
}

// ---------------------------------------------------------------------------
extern "C" void kernel_launch(void* const* d_in, const int* in_sizes, int n_in,
                              void* d_out, int out_size)
{
    const float* x   = nullptr;
    const int*   sol = nullptr;
    const float* W   = nullptr;
    const float* pat = nullptr;

    for (int i = 0; i < n_in; i++) {
        switch (in_sizes[i]) {
            case ROWS * 2: x   = (const float*)d_in[i]; break;  // x
            case ROWS:     sol = (const int*)  d_in[i]; break;  // solutions
            case 256:      W   = (const float*)d_in[i]; break;  // W
            case SS * DD:  pat = (const float*)d_in[i]; break;  // pattern
            default: break;
        }
    }

    float* out = (float*)d_out;

    const int write_pos = (out_size >= 2 * A_EL) ? 1 : 0;
    const int write_vt  = (out_size >= 2 * A_EL + ROWS) ? 1 : 0;
    const int write_t2  = (out_size >= 2 * A_EL + 3 * ROWS) ? 1 : 0;

    float*  out_vt = out + (size_t)2 * A_EL;
    float2* out_t2 = (float2*)(out + (size_t)2 * A_EL + ROWS);

    fused_kernel<<<CHASE_BLOCKS + EMB_BLOCKS, 256>>>(
        sol, (const float2*)x, (const float4*)W,
        out, out_vt, out_t2, write_vt, write_t2);

    if (write_pos)
        pos_kernel<<<EMB_BLOCKS, 256>>>(
            (const float4*)pat, out + (size_t)A_EL);
}